// round 13
// baseline (speedup 1.0000x reference)
#include <cuda_runtime.h>

#define DATA_NUM 1024
#define CLS_NUM  32000
#define NB       2048            // histogram bins (both levels)
#define NT       256             // threads per CTA
#define BPT      (NB / NT)       // 8 bins per thread
#define RANGE2   140.0f          // log2-domain window below the M2 bound
#define CAP      1536            // stash capacity for crossing-bin elements
#define LOG2E    1.4426950408889634f
#define LN2      0.6931471805599453f

// Guaranteed-scalar 32-bit load for the tiny h vectors.
__device__ __forceinline__ float vload(const float* p) {
    return *(const volatile float*)p;
}

// Bare MUFU exponential (base 2) — fast regardless of compile flags.
__device__ __forceinline__ float ex2(float x) {
    float y;
    asm("ex2.approx.f32 %0, %1;" : "=f"(y) : "f"(x));
    return y;
}

// Fused block-wide sum of 4 values. red: 4*NT floats. Broadcasts results.
__device__ void block_sum4(float& a, float& b, float& c, float& d, float* red) {
    int tid = threadIdx.x;
    __syncthreads();
    red[tid] = a; red[NT + tid] = b; red[2 * NT + tid] = c; red[3 * NT + tid] = d;
    __syncthreads();
#pragma unroll
    for (int s = NT / 2; s > 0; s >>= 1) {
        if (tid < s) {
            red[tid]          += red[tid + s];
            red[NT + tid]     += red[NT + tid + s];
            red[2 * NT + tid] += red[2 * NT + tid + s];
            red[3 * NT + tid] += red[3 * NT + tid + s];
        }
        __syncthreads();
    }
    a = red[0]; b = red[NT]; c = red[2 * NT]; d = red[3 * NT];
    __syncthreads();
}

// Find bin where ascending cumulative mass crosses `target`.
__device__ void find_crossing(const float* hist, float* red, float target,
                              int* s_bin, float* s_cdf) {
    int tid = threadIdx.x;
    __syncthreads();
    if (tid == 0) { *s_bin = NB - 1; *s_cdf = 0.f; }   // safe default
    float h[BPT];
    float s = 0.f;
#pragma unroll
    for (int i = 0; i < BPT; i++) { h[i] = hist[tid * BPT + i]; s += h[i]; }
    red[tid] = s;
    __syncthreads();
    if (tid == 0) {
        float c = 0.f;
        for (int i = 0; i < NT; i++) { float t = red[i]; red[i] = c; c += t; }
    }
    __syncthreads();
    float c = red[tid];
#pragma unroll
    for (int i = 0; i < BPT; i++) {
        if (c < target && c + h[i] >= target) { *s_bin = tid * BPT + i; *s_cdf = c; }
        c += h[i];
    }
    __syncthreads();
}

// ---------------------------------------------------------------------------
__global__ void zero_out(float* out) { out[0] = 0.f; }

// One CTA per data row. 4 CTAs/SM target (64 regs, ~31 KB smem).
__global__ void __launch_bounds__(NT, 4) akl_kernel(
    const float* h1, const float* e1,
    const float* h3, const float* e3, float* out)
{
    __shared__ float hist[NB];          // 8 KB
    __shared__ float red[4 * NT];       // 4 KB
    __shared__ float st_l2[CAP];        // 6 KB
    __shared__ float st_u2[CAP];        // 6 KB
    __shared__ float st_gap[CAP];       // 6 KB
    __shared__ int   s_cnt;
    __shared__ float s_cdf1, s_cdf2;
    __shared__ int   s_b1,   s_b2;

    const int row = blockIdx.x;
    const int tid = threadIdx.x;

    // Row coefficients pre-scaled by log2(e): all logits in log2 domain.
    const float a1 = vload(h1 + 2 * row) * LOG2E, b1v = vload(h1 + 2 * row + 1) * LOG2E;
    const float a3 = vload(h3 + 2 * row) * LOG2E, b3v = vload(h3 + 2 * row + 1) * LOG2E;
    // Analytic bound: |l| <= ||h'||*max||e_j||; max 2-D N(0,1) norm over 32k
    // draws < 6 w.o.p. Softmax shift-invariance makes any bound exact.
    const float M1 = 6.0f * sqrtf(a1 * a1 + b1v * b1v);
    const float M2 = 6.0f * sqrtf(a3 * a3 + b3v * b3v);
    const float nM1 = -M1, nM2 = -M2;          // folded into the logit FMA
    const float dM  = M2 - M1;                  // l2-l1 = (l2m-l1m)+dM
    const float invw = (float)NB / RANGE2;      // level-1 bin scale
    // bin = (l2 - (M2-RANGE2))*invw = l2m*invw + NB
    const float bias1 = (float)NB;

    const float2* e1v = (const float2*)e1;
    const float2* e3v = (const float2*)e3;

    for (int b = tid; b < NB; b += NT) hist[b] = 0.f;
    if (tid == 0) s_cnt = 0;
    __syncthreads();

    // ---- Pass 1: Z/S sums + level-1 histogram (unroll 2, lean live set)
    float Z1 = 0.f, Z2 = 0.f, S1 = 0.f, S2 = 0.f;
    {
        int j = tid;
        for (; j + NT < CLS_NUM; j += 2 * NT) {
            float2 w1a = __ldg(e1v + j), w1b = __ldg(e1v + j + NT);
            float2 w3a = __ldg(e3v + j), w3b = __ldg(e3v + j + NT);
#pragma unroll
            for (int u = 0; u < 2; u++) {
                float2 v1 = u ? w1b : w1a;
                float2 v3 = u ? w3b : w3a;
                float l1m = fmaf(a1, v1.x, fmaf(b1v, v1.y, nM1));
                float l2m = fmaf(a3, v3.x, fmaf(b3v, v3.y, nM2));
                float u1 = ex2(l1m);
                float u2 = ex2(l2m);
                Z1 += u1; Z2 += u2;
                float dl = (l2m - l1m) + dM;
                S2 = fmaf(u2,  dl, S2);
                S1 = fmaf(u1, -dl, S1);
                float bf = fmaf(l2m, invw, bias1);
                int b = (int)fminf(fmaxf(bf, 0.f), (float)(NB - 1));
                atomicAdd(&hist[b], u2);
            }
        }
        for (; j < CLS_NUM; j += NT) {
            float2 v1 = __ldg(e1v + j);
            float2 v3 = __ldg(e3v + j);
            float l1m = fmaf(a1, v1.x, fmaf(b1v, v1.y, nM1));
            float l2m = fmaf(a3, v3.x, fmaf(b3v, v3.y, nM2));
            float u1 = ex2(l1m);
            float u2 = ex2(l2m);
            Z1 += u1; Z2 += u2;
            float dl = (l2m - l1m) + dM;
            S2 = fmaf(u2,  dl, S2);
            S1 = fmaf(u1, -dl, S1);
            float bf = fmaf(l2m, invw, bias1);
            int b = (int)fminf(fmaxf(bf, 0.f), (float)(NB - 1));
            atomicAdd(&hist[b], u2);
        }
    }
    block_sum4(Z1, Z2, S1, S2, red);
    const float halfZ2 = 0.5f * Z2;

    // ---- Level-1 crossing bin
    find_crossing(hist, red, halfZ2, &s_b1, &s_cdf1);
    const int   b1   = s_b1;
    const float cdf1 = s_cdf1;

    // Level-2 geometry: s = (l2 - lo1)*invw2 = l2m*invw2 + bias2
    const float w1w   = RANGE2 / (float)NB;
    const float invw2 = (float)NB / w1w;
    const float bias2 = ((float)NB - (float)b1) * (float)NB;  // (RANGE2-b1*w1w)*invw2

    __syncthreads();
    for (int b = tid; b < NB; b += NT) hist[b] = 0.f;   // reuse for level-2
    __syncthreads();

    // ---- Pass 2: gap sums; crossing-bin elems -> sub-hist + stash
    const float invZ1 = 1.0f / Z1, invZ2 = 1.0f / Z2;
    float gh = 0.f, gt = 0.f;
    {
        int j = tid;
        for (; j + NT < CLS_NUM; j += 2 * NT) {
            float2 w1a = __ldg(e1v + j), w1b = __ldg(e1v + j + NT);
            float2 w3a = __ldg(e3v + j), w3b = __ldg(e3v + j + NT);
#pragma unroll
            for (int u = 0; u < 2; u++) {
                float2 v1 = u ? w1b : w1a;
                float2 v3 = u ? w3b : w3a;
                float l1m = fmaf(a1, v1.x, fmaf(b1v, v1.y, nM1));
                float l2m = fmaf(a3, v3.x, fmaf(b3v, v3.y, nM2));
                float u2 = ex2(l2m);
                float gap = fabsf(u2 * invZ2 - ex2(l1m) * invZ1);
                float bf = fmaf(l2m, invw, bias1);
                int b = (int)fminf(fmaxf(bf, 0.f), (float)(NB - 1));
                if (b < b1)      gt += gap;
                else if (b > b1) gh += gap;
                else {
                    float sf = fmaf(l2m, invw2, bias2);
                    int s = (int)fminf(fmaxf(sf, 0.f), (float)(NB - 1));
                    atomicAdd(&hist[s], u2);
                    int idx = atomicAdd(&s_cnt, 1);
                    if (idx < CAP) { st_l2[idx] = l2m; st_u2[idx] = u2; st_gap[idx] = gap; }
                }
            }
        }
        for (; j < CLS_NUM; j += NT) {
            float2 v1 = __ldg(e1v + j);
            float2 v3 = __ldg(e3v + j);
            float l1m = fmaf(a1, v1.x, fmaf(b1v, v1.y, nM1));
            float l2m = fmaf(a3, v3.x, fmaf(b3v, v3.y, nM2));
            float u2 = ex2(l2m);
            float gap = fabsf(u2 * invZ2 - ex2(l1m) * invZ1);
            float bf = fmaf(l2m, invw, bias1);
            int b = (int)fminf(fmaxf(bf, 0.f), (float)(NB - 1));
            if (b < b1)      gt += gap;
            else if (b > b1) gh += gap;
            else {
                float sf = fmaf(l2m, invw2, bias2);
                int s = (int)fminf(fmaxf(sf, 0.f), (float)(NB - 1));
                atomicAdd(&hist[s], u2);
                int idx = atomicAdd(&s_cnt, 1);
                if (idx < CAP) { st_l2[idx] = l2m; st_u2[idx] = u2; st_gap[idx] = gap; }
            }
        }
    }

    // ---- Level-2 crossing within the sub-histogram
    find_crossing(hist, red, halfZ2 - cdf1, &s_b2, &s_cdf2);
    const int   b2   = s_b2;
    const float cdf2 = cdf1 + s_cdf2;
    __syncthreads();
    const int m = s_cnt;

    if (m <= CAP) {
        for (int i = tid; i < m; i += NT) {
            float sf = fmaf(st_l2[i], invw2, bias2);
            int s = (int)fminf(fmaxf(sf, 0.f), (float)(NB - 1));
            bool tail;
            if (s != b2) tail = (s < b2);
            else         tail = (cdf2 + st_u2[i]) < halfZ2;
            if (tail) gt += st_gap[i]; else gh += st_gap[i];
        }
    } else {
        // Rare degenerate row: exact rescan of crossing-bin elements
        for (int j = tid; j < CLS_NUM; j += NT) {
            float2 v3 = __ldg(e3v + j);
            float l2m = fmaf(a3, v3.x, fmaf(b3v, v3.y, nM2));
            float bf = fmaf(l2m, invw, bias1);
            int b = (int)fminf(fmaxf(bf, 0.f), (float)(NB - 1));
            if (b == b1) {
                float2 v1 = __ldg(e1v + j);
                float l1m = fmaf(a1, v1.x, fmaf(b1v, v1.y, nM1));
                float u2 = ex2(l2m);
                float gap = fabsf(u2 * invZ2 - ex2(l1m) * invZ1);
                float sf = fmaf(l2m, invw2, bias2);
                int s = (int)fminf(fmaxf(sf, 0.f), (float)(NB - 1));
                bool tail;
                if (s != b2) tail = (s < b2);
                else         tail = (cdf2 + u2) < halfZ2;
                if (tail) gt += gap; else gh += gap;
            }
        }
    }
    {
        float d0 = 0.f, d1 = 0.f;
        block_sum4(gh, gt, d0, d1, red);
    }

    if (tid == 0) {
        // log2-domain sums -> nats
        float C21 = LN2 * (M2 - M1) + (__logf(Z2) - __logf(Z1));
        float fkl = LN2 * S2 / Z2 - C21;
        float rkl = LN2 * S1 / Z1 + C21;
        float denom = gh + gt;
        float akl = (gh * fkl + gt * rkl) / denom;
        atomicAdd(out, akl * (1.0f / (float)DATA_NUM));
    }
}

// ---------------------------------------------------------------------------
extern "C" void kernel_launch(void* const* d_in, const int* in_sizes, int n_in,
                              void* d_out, int out_size) {
    const float *h1 = 0, *h3 = 0, *e1 = 0, *e3 = 0;
    for (int i = 0; i < n_in; i++) {
        int s = in_sizes[i];
        if (s == 2 * DATA_NUM || s == 2 * DATA_NUM * 4) {
            if (!h1) h1 = (const float*)d_in[i]; else if (!h3) h3 = (const float*)d_in[i];
        } else if (s == 2 * CLS_NUM || s == 2 * CLS_NUM * 4) {
            if (!e1) e1 = (const float*)d_in[i]; else if (!e3) e3 = (const float*)d_in[i];
        }
    }
    if (!h1 || !h3 || !e1 || !e3) {
        h1 = (const float*)d_in[0];
        e1 = (const float*)d_in[1];
        h3 = (const float*)d_in[2];
        e3 = (const float*)d_in[3];
    }

    float* out = (float*)d_out;
    zero_out<<<1, 1>>>(out);
    akl_kernel<<<DATA_NUM, NT>>>(h1, e1, h3, e3, out);
}

// round 14
// speedup vs baseline: 2.0748x; 2.0748x over previous
#include <cuda_runtime.h>

#define DATA_NUM 1024
#define CLS_NUM  32000
#define NBG      2048            // level-1 (global) histogram bins
#define NB2      2048            // level-2 (smem) sub-histogram bins
#define NT       256             // threads per CTA
#define BPTG     (NBG / NT)      // 8 global bins per thread
#define BPT2     (NB2 / NT)      // 8 smem bins per thread
#define RANGE2   140.0f          // log2-domain window below the M2 bound
#define CAP      4096            // stash capacity for crossing-bin elements
#define LOG2E    1.4426950408889634f
#define LN2      0.6931471805599453f

// Per-row global histogram scratch (8 MB). Zeroed by each CTA for its row.
__device__ float g_hist[DATA_NUM][NBG];

// Guaranteed-scalar 32-bit load for the tiny h vectors.
__device__ __forceinline__ float vload(const float* p) {
    return *(const volatile float*)p;
}

// Bare MUFU exponential (base 2) — fast regardless of compile flags.
__device__ __forceinline__ float ex2(float x) {
    float y;
    asm("ex2.approx.f32 %0, %1;" : "=f"(y) : "f"(x));
    return y;
}

// Block-wide sum via shared-memory tree. red: NT floats.
__device__ float block_sum(float v, float* red) {
    int tid = threadIdx.x;
    __syncthreads();
    red[tid] = v;
    __syncthreads();
#pragma unroll
    for (int s = NT / 2; s > 0; s >>= 1) {
        if (tid < s) red[tid] += red[tid + s];
        __syncthreads();
    }
    float r = red[0];
    __syncthreads();
    return r;
}

// Find bin where ascending cumulative mass crosses `target` in hist[NBINS].
// NBINS == BPT*NT. Works for global or shared source. Ends synced.
template <int NBINS, int BPT>
__device__ void find_crossing(const float* hist, float* red, float target,
                              int* s_bin, float* s_cdf) {
    int tid = threadIdx.x;
    __syncthreads();
    if (tid == 0) { *s_bin = NBINS - 1; *s_cdf = 0.f; }   // safe default
    float h[BPT];
    float s = 0.f;
#pragma unroll
    for (int i = 0; i < BPT; i++) { h[i] = hist[tid * BPT + i]; s += h[i]; }
    red[tid] = s;
    __syncthreads();
    if (tid == 0) {
        float c = 0.f;
        for (int i = 0; i < NT; i++) { float t = red[i]; red[i] = c; c += t; }
    }
    __syncthreads();
    float c = red[tid];
#pragma unroll
    for (int i = 0; i < BPT; i++) {
        if (c < target && c + h[i] >= target) { *s_bin = tid * BPT + i; *s_cdf = c; }
        c += h[i];
    }
    __syncthreads();
}

// ---------------------------------------------------------------------------
__global__ void zero_out(float* out) { out[0] = 0.f; }

// One CTA per data row.
__global__ void __launch_bounds__(NT) akl_kernel(
    const float* h1, const float* e1,
    const float* h3, const float* e3, float* out)
{
    __shared__ float hist2[NB2];        // 8 KB (level-2 sub-hist)
    __shared__ float red[NT];           // 1 KB
    __shared__ float st_l2[CAP];        // 16 KB
    __shared__ float st_u2[CAP];        // 16 KB
    __shared__ float st_gap[CAP];       // 16 KB
    __shared__ int   s_cnt;
    __shared__ float s_cdf1, s_cdf2;
    __shared__ int   s_b1,   s_b2;

    const int row = blockIdx.x;
    const int tid = threadIdx.x;
    float* ghist = g_hist[row];

    // Row coefficients pre-scaled by log2(e): all logits in log2 domain.
    const float a1 = vload(h1 + 2 * row) * LOG2E, b1v = vload(h1 + 2 * row + 1) * LOG2E;
    const float a3 = vload(h3 + 2 * row) * LOG2E, b3v = vload(h3 + 2 * row + 1) * LOG2E;
    // Analytic bound: |l| <= ||h'||*max||e_j||; max 2-D N(0,1) norm over 32k
    // draws < 6 w.o.p. Softmax shift-invariance makes any bound exact.
    const float M1 = 6.0f * sqrtf(a1 * a1 + b1v * b1v);
    const float M2 = 6.0f * sqrtf(a3 * a3 + b3v * b3v);
    const float nM1 = -M1, nM2 = -M2;
    const float dM  = M2 - M1;                  // l2-l1 = (l2m-l1m)+dM
    const float invw1 = (float)NBG / RANGE2;    // level-1 bin = l2m*invw1 + NBG
    const float bias1 = (float)NBG;

    const float2* e1v = (const float2*)e1;
    const float2* e3v = (const float2*)e3;

    // Zero this row's global histogram (fresh every launch/replay).
#pragma unroll
    for (int i = 0; i < BPTG; i++) ghist[tid + i * NT] = 0.f;
    if (tid == 0) s_cnt = 0;
    __threadfence();
    __syncthreads();

    // ---- Pass 1: Z/S sums + level-1 histogram via fire-and-forget RED.
    float Z1 = 0.f, Z2 = 0.f, S1 = 0.f, S2 = 0.f;
    {
        int j = tid;
        for (; j + 3 * NT < CLS_NUM; j += 4 * NT) {
            float2 w1[4], w3[4];
#pragma unroll
            for (int u = 0; u < 4; u++) { w1[u] = __ldg(e1v + j + u * NT); }
#pragma unroll
            for (int u = 0; u < 4; u++) { w3[u] = __ldg(e3v + j + u * NT); }
#pragma unroll
            for (int u = 0; u < 4; u++) {
                float l1m = fmaf(a1, w1[u].x, fmaf(b1v, w1[u].y, nM1));
                float l2m = fmaf(a3, w3[u].x, fmaf(b3v, w3[u].y, nM2));
                float u1 = ex2(l1m);
                float u2 = ex2(l2m);
                Z1 += u1; Z2 += u2;
                float dl = (l2m - l1m) + dM;
                S2 = fmaf(u2,  dl, S2);
                S1 = fmaf(u1, -dl, S1);
                float bf = fmaf(l2m, invw1, bias1);
                int b = (int)fminf(fmaxf(bf, 0.f), (float)(NBG - 1));
                atomicAdd(&ghist[b], u2);   // result unused -> RED (no return)
            }
        }
        for (; j < CLS_NUM; j += NT) {
            float2 v1 = __ldg(e1v + j);
            float2 v3 = __ldg(e3v + j);
            float l1m = fmaf(a1, v1.x, fmaf(b1v, v1.y, nM1));
            float l2m = fmaf(a3, v3.x, fmaf(b3v, v3.y, nM2));
            float u1 = ex2(l1m);
            float u2 = ex2(l2m);
            Z1 += u1; Z2 += u2;
            float dl = (l2m - l1m) + dM;
            S2 = fmaf(u2,  dl, S2);
            S1 = fmaf(u1, -dl, S1);
            float bf = fmaf(l2m, invw1, bias1);
            int b = (int)fminf(fmaxf(bf, 0.f), (float)(NBG - 1));
            atomicAdd(&ghist[b], u2);
        }
    }
    Z1 = block_sum(Z1, red);
    Z2 = block_sum(Z2, red);
    S1 = block_sum(S1, red);
    S2 = block_sum(S2, red);
    const float halfZ2 = 0.5f * Z2;

    // Make this CTA's RED results visible to its own subsequent loads.
    __threadfence();
    __syncthreads();

    // ---- Level-1 crossing bin (read back from global)
    find_crossing<NBG, BPTG>(ghist, red, halfZ2, &s_b1, &s_cdf1);
    const int   b1   = s_b1;
    const float cdf1 = s_cdf1;

    // Level-2 geometry: s = l2m*invw2 + bias2 within bin b1
    const float w1w   = RANGE2 / (float)NBG;
    const float invw2 = (float)NB2 / w1w;
    const float bias2 = (float)NB2 * ((float)NBG - (float)b1);

    __syncthreads();
    for (int b = tid; b < NB2; b += NT) hist2[b] = 0.f;
    __syncthreads();

    // ---- Pass 2: gap sums; crossing-bin elems -> smem sub-hist + stash
    const float invZ1 = 1.0f / Z1, invZ2 = 1.0f / Z2;
    float gh = 0.f, gt = 0.f;
    {
        int j = tid;
        for (; j + 3 * NT < CLS_NUM; j += 4 * NT) {
            float2 w1[4], w3[4];
#pragma unroll
            for (int u = 0; u < 4; u++) { w1[u] = __ldg(e1v + j + u * NT); }
#pragma unroll
            for (int u = 0; u < 4; u++) { w3[u] = __ldg(e3v + j + u * NT); }
#pragma unroll
            for (int u = 0; u < 4; u++) {
                float l1m = fmaf(a1, w1[u].x, fmaf(b1v, w1[u].y, nM1));
                float l2m = fmaf(a3, w3[u].x, fmaf(b3v, w3[u].y, nM2));
                float u2 = ex2(l2m);
                float gap = fabsf(u2 * invZ2 - ex2(l1m) * invZ1);
                float bf = fmaf(l2m, invw1, bias1);
                int b = (int)fminf(fmaxf(bf, 0.f), (float)(NBG - 1));
                if (b < b1)      gt += gap;
                else if (b > b1) gh += gap;
                else {
                    float sf = fmaf(l2m, invw2, bias2);
                    int s = (int)fminf(fmaxf(sf, 0.f), (float)(NB2 - 1));
                    atomicAdd(&hist2[s], u2);
                    int idx = atomicAdd(&s_cnt, 1);
                    if (idx < CAP) { st_l2[idx] = l2m; st_u2[idx] = u2; st_gap[idx] = gap; }
                }
            }
        }
        for (; j < CLS_NUM; j += NT) {
            float2 v1 = __ldg(e1v + j);
            float2 v3 = __ldg(e3v + j);
            float l1m = fmaf(a1, v1.x, fmaf(b1v, v1.y, nM1));
            float l2m = fmaf(a3, v3.x, fmaf(b3v, v3.y, nM2));
            float u2 = ex2(l2m);
            float gap = fabsf(u2 * invZ2 - ex2(l1m) * invZ1);
            float bf = fmaf(l2m, invw1, bias1);
            int b = (int)fminf(fmaxf(bf, 0.f), (float)(NBG - 1));
            if (b < b1)      gt += gap;
            else if (b > b1) gh += gap;
            else {
                float sf = fmaf(l2m, invw2, bias2);
                int s = (int)fminf(fmaxf(sf, 0.f), (float)(NB2 - 1));
                atomicAdd(&hist2[s], u2);
                int idx = atomicAdd(&s_cnt, 1);
                if (idx < CAP) { st_l2[idx] = l2m; st_u2[idx] = u2; st_gap[idx] = gap; }
            }
        }
    }

    // ---- Level-2 crossing within the smem sub-histogram
    find_crossing<NB2, BPT2>(hist2, red, halfZ2 - cdf1, &s_b2, &s_cdf2);
    const int   b2   = s_b2;
    const float cdf2 = cdf1 + s_cdf2;
    __syncthreads();
    const int m = s_cnt;

    if (m <= CAP) {
        for (int i = tid; i < m; i += NT) {
            float sf = fmaf(st_l2[i], invw2, bias2);
            int s = (int)fminf(fmaxf(sf, 0.f), (float)(NB2 - 1));
            bool tail;
            if (s != b2) tail = (s < b2);
            else         tail = (cdf2 + st_u2[i]) < halfZ2;
            if (tail) gt += st_gap[i]; else gh += st_gap[i];
        }
    } else {
        // Rare degenerate row: exact rescan of crossing-bin elements
        for (int j = tid; j < CLS_NUM; j += NT) {
            float2 v3 = __ldg(e3v + j);
            float l2m = fmaf(a3, v3.x, fmaf(b3v, v3.y, nM2));
            float bf = fmaf(l2m, invw1, bias1);
            int b = (int)fminf(fmaxf(bf, 0.f), (float)(NBG - 1));
            if (b == b1) {
                float2 v1 = __ldg(e1v + j);
                float l1m = fmaf(a1, v1.x, fmaf(b1v, v1.y, nM1));
                float u2 = ex2(l2m);
                float gap = fabsf(u2 * invZ2 - ex2(l1m) * invZ1);
                float sf = fmaf(l2m, invw2, bias2);
                int s = (int)fminf(fmaxf(sf, 0.f), (float)(NB2 - 1));
                bool tail;
                if (s != b2) tail = (s < b2);
                else         tail = (cdf2 + u2) < halfZ2;
                if (tail) gt += gap; else gh += gap;
            }
        }
    }
    gh = block_sum(gh, red);
    gt = block_sum(gt, red);

    if (tid == 0) {
        // log2-domain sums -> nats
        float C21 = LN2 * (M2 - M1) + (__logf(Z2) - __logf(Z1));
        float fkl = LN2 * S2 / Z2 - C21;
        float rkl = LN2 * S1 / Z1 + C21;
        float denom = gh + gt;
        float akl = (gh * fkl + gt * rkl) / denom;
        atomicAdd(out, akl * (1.0f / (float)DATA_NUM));
    }
}

// ---------------------------------------------------------------------------
extern "C" void kernel_launch(void* const* d_in, const int* in_sizes, int n_in,
                              void* d_out, int out_size) {
    const float *h1 = 0, *h3 = 0, *e1 = 0, *e3 = 0;
    for (int i = 0; i < n_in; i++) {
        int s = in_sizes[i];
        if (s == 2 * DATA_NUM || s == 2 * DATA_NUM * 4) {
            if (!h1) h1 = (const float*)d_in[i]; else if (!h3) h3 = (const float*)d_in[i];
        } else if (s == 2 * CLS_NUM || s == 2 * CLS_NUM * 4) {
            if (!e1) e1 = (const float*)d_in[i]; else if (!e3) e3 = (const float*)d_in[i];
        }
    }
    if (!h1 || !h3 || !e1 || !e3) {
        h1 = (const float*)d_in[0];
        e1 = (const float*)d_in[1];
        h3 = (const float*)d_in[2];
        e3 = (const float*)d_in[3];
    }

    float* out = (float*)d_out;
    zero_out<<<1, 1>>>(out);
    akl_kernel<<<DATA_NUM, NT>>>(h1, e1, h3, e3, out);
}

// round 15
// speedup vs baseline: 2.0911x; 1.0078x over previous
#include <cuda_runtime.h>

#define DATA_NUM 1024
#define CLS_NUM  32000
#define NBG      512             // level-1 (global) histogram bins
#define NB2      2048            // level-2 (smem) sub-histogram bins
#define NT       256             // threads per CTA
#define BPTG     (NBG / NT)      // 2 global bins per thread
#define BPT2     (NB2 / NT)      // 8 smem bins per thread
#define RANGE2   140.0f          // log2-domain window below the M2 bound
#define CAP      4096            // stash capacity for crossing-bin elements
#define LOG2E    1.4426950408889634f
#define LN2      0.6931471805599453f

// Per-row global histogram scratch (2 MB). Zeroed by each CTA for its row.
__device__ float g_hist[DATA_NUM][NBG];

// Guaranteed-scalar 32-bit load for the tiny h vectors.
__device__ __forceinline__ float vload(const float* p) {
    return *(const volatile float*)p;
}

// Bare MUFU exponential (base 2) — fast regardless of compile flags.
__device__ __forceinline__ float ex2(float x) {
    float y;
    asm("ex2.approx.f32 %0, %1;" : "=f"(y) : "f"(x));
    return y;
}

// Block-wide sum via shared-memory tree. red: NT floats.
__device__ float block_sum(float v, float* red) {
    int tid = threadIdx.x;
    __syncthreads();
    red[tid] = v;
    __syncthreads();
#pragma unroll
    for (int s = NT / 2; s > 0; s >>= 1) {
        if (tid < s) red[tid] += red[tid + s];
        __syncthreads();
    }
    float r = red[0];
    __syncthreads();
    return r;
}

// Find bin where ascending cumulative mass crosses `target` in hist[NBINS].
template <int NBINS, int BPT>
__device__ void find_crossing(const float* hist, float* red, float target,
                              int* s_bin, float* s_cdf) {
    int tid = threadIdx.x;
    __syncthreads();
    if (tid == 0) { *s_bin = NBINS - 1; *s_cdf = 0.f; }   // safe default
    float h[BPT];
    float s = 0.f;
#pragma unroll
    for (int i = 0; i < BPT; i++) { h[i] = hist[tid * BPT + i]; s += h[i]; }
    red[tid] = s;
    __syncthreads();
    if (tid == 0) {
        float c = 0.f;
        for (int i = 0; i < NT; i++) { float t = red[i]; red[i] = c; c += t; }
    }
    __syncthreads();
    float c = red[tid];
#pragma unroll
    for (int i = 0; i < BPT; i++) {
        if (c < target && c + h[i] >= target) { *s_bin = tid * BPT + i; *s_cdf = c; }
        c += h[i];
    }
    __syncthreads();
}

// ---------------------------------------------------------------------------
__global__ void zero_out(float* out) { out[0] = 0.f; }

// One CTA per data row.
__global__ void __launch_bounds__(NT) akl_kernel(
    const float* h1, const float* e1,
    const float* h3, const float* e3, float* out)
{
    __shared__ float hist2[NB2];        // 8 KB (level-2 sub-hist)
    __shared__ float red[NT];           // 1 KB
    __shared__ float st_l2[CAP];        // 16 KB
    __shared__ float st_u2[CAP];        // 16 KB
    __shared__ float st_gap[CAP];       // 16 KB
    __shared__ int   s_cnt;
    __shared__ float s_cdf1, s_cdf2;
    __shared__ int   s_b1,   s_b2;

    const int row = blockIdx.x;
    const int tid = threadIdx.x;
    float* ghist = g_hist[row];

    // Row coefficients pre-scaled by log2(e): all logits in log2 domain.
    const float a1 = vload(h1 + 2 * row) * LOG2E, b1v = vload(h1 + 2 * row + 1) * LOG2E;
    const float a3 = vload(h3 + 2 * row) * LOG2E, b3v = vload(h3 + 2 * row + 1) * LOG2E;
    // Analytic bound: |l| <= ||h'||*max||e_j||; max 2-D N(0,1) norm over 32k
    // draws < 6 w.o.p. Softmax shift-invariance makes any bound exact.
    const float M1 = 6.0f * sqrtf(a1 * a1 + b1v * b1v);
    const float M2 = 6.0f * sqrtf(a3 * a3 + b3v * b3v);
    const float nM1 = -M1, nM2 = -M2;
    const float dM  = M2 - M1;                  // l2-l1 = (l2m-l1m)+dM
    const float invw1 = (float)NBG / RANGE2;    // level-1 bin = l2m*invw1 + NBG
    const float bias1 = (float)NBG;

    const float2* e1v = (const float2*)e1;
    const float2* e3v = (const float2*)e3;

    // Zero this row's global histogram (fresh every launch/replay).
#pragma unroll
    for (int i = 0; i < BPTG; i++) ghist[tid + i * NT] = 0.f;
    if (tid == 0) s_cnt = 0;
    __threadfence();
    __syncthreads();

    // ---- Pass 1: Z/S sums + level-1 histogram via fire-and-forget RED.
    float Z1 = 0.f, Z2 = 0.f, S1 = 0.f, S2 = 0.f;
    {
        int j = tid;
        for (; j + 3 * NT < CLS_NUM; j += 4 * NT) {
            float2 w1[4], w3[4];
#pragma unroll
            for (int u = 0; u < 4; u++) { w1[u] = __ldg(e1v + j + u * NT); }
#pragma unroll
            for (int u = 0; u < 4; u++) { w3[u] = __ldg(e3v + j + u * NT); }
#pragma unroll
            for (int u = 0; u < 4; u++) {
                float l1m = fmaf(a1, w1[u].x, fmaf(b1v, w1[u].y, nM1));
                float l2m = fmaf(a3, w3[u].x, fmaf(b3v, w3[u].y, nM2));
                float u1 = ex2(l1m);
                float u2 = ex2(l2m);
                Z1 += u1; Z2 += u2;
                float dl = (l2m - l1m) + dM;
                S2 = fmaf(u2,  dl, S2);
                S1 = fmaf(u1, -dl, S1);
                float bf = fmaf(l2m, invw1, bias1);
                int b = (int)fminf(fmaxf(bf, 0.f), (float)(NBG - 1));
                atomicAdd(&ghist[b], u2);   // result unused -> RED (no return)
            }
        }
        for (; j < CLS_NUM; j += NT) {
            float2 v1 = __ldg(e1v + j);
            float2 v3 = __ldg(e3v + j);
            float l1m = fmaf(a1, v1.x, fmaf(b1v, v1.y, nM1));
            float l2m = fmaf(a3, v3.x, fmaf(b3v, v3.y, nM2));
            float u1 = ex2(l1m);
            float u2 = ex2(l2m);
            Z1 += u1; Z2 += u2;
            float dl = (l2m - l1m) + dM;
            S2 = fmaf(u2,  dl, S2);
            S1 = fmaf(u1, -dl, S1);
            float bf = fmaf(l2m, invw1, bias1);
            int b = (int)fminf(fmaxf(bf, 0.f), (float)(NBG - 1));
            atomicAdd(&ghist[b], u2);
        }
    }
    Z1 = block_sum(Z1, red);
    Z2 = block_sum(Z2, red);
    S1 = block_sum(S1, red);
    S2 = block_sum(S2, red);
    const float halfZ2 = 0.5f * Z2;

    // Make this CTA's RED results visible to its own subsequent loads.
    __threadfence();
    __syncthreads();

    // ---- Level-1 crossing bin (read back from global)
    find_crossing<NBG, BPTG>(ghist, red, halfZ2, &s_b1, &s_cdf1);
    const int   b1   = s_b1;
    const float cdf1 = s_cdf1;

    // Thresholds replicating clamped-floor bin semantics on the 99% path:
    // floor(clamp(bf)) <  b1  <=>  clamp(bf) <  b1
    // floor(clamp(bf)) >  b1  <=>  clamp(bf) >= b1+1
    const float b1f = (float)b1, b1f1 = (float)(b1 + 1);

    // Level-2 geometry: s = l2m*invw2 + bias2 within bin b1
    const float w1w   = RANGE2 / (float)NBG;
    const float invw2 = (float)NB2 / w1w;
    const float bias2 = (float)NB2 * ((float)NBG - (float)b1);

    __syncthreads();
    for (int b = tid; b < NB2; b += NT) hist2[b] = 0.f;
    __syncthreads();

    // ---- Pass 2: gap sums; crossing-bin elems -> smem sub-hist + stash
    const float invZ1 = 1.0f / Z1, invZ2 = 1.0f / Z2;
    float gh = 0.f, gt = 0.f;
    {
        int j = tid;
        for (; j + 3 * NT < CLS_NUM; j += 4 * NT) {
            float2 w1[4], w3[4];
#pragma unroll
            for (int u = 0; u < 4; u++) { w1[u] = __ldg(e1v + j + u * NT); }
#pragma unroll
            for (int u = 0; u < 4; u++) { w3[u] = __ldg(e3v + j + u * NT); }
#pragma unroll
            for (int u = 0; u < 4; u++) {
                float l1m = fmaf(a1, w1[u].x, fmaf(b1v, w1[u].y, nM1));
                float l2m = fmaf(a3, w3[u].x, fmaf(b3v, w3[u].y, nM2));
                float u2 = ex2(l2m);
                float gap = fabsf(u2 * invZ2 - ex2(l1m) * invZ1);
                float bfc = fminf(fmaxf(fmaf(l2m, invw1, bias1), 0.f), (float)(NBG - 1));
                if (bfc < b1f)        gt += gap;
                else if (bfc >= b1f1) gh += gap;
                else {
                    float sf = fmaf(l2m, invw2, bias2);
                    int s = (int)fminf(fmaxf(sf, 0.f), (float)(NB2 - 1));
                    atomicAdd(&hist2[s], u2);
                    int idx = atomicAdd(&s_cnt, 1);
                    if (idx < CAP) { st_l2[idx] = l2m; st_u2[idx] = u2; st_gap[idx] = gap; }
                }
            }
        }
        for (; j < CLS_NUM; j += NT) {
            float2 v1 = __ldg(e1v + j);
            float2 v3 = __ldg(e3v + j);
            float l1m = fmaf(a1, v1.x, fmaf(b1v, v1.y, nM1));
            float l2m = fmaf(a3, v3.x, fmaf(b3v, v3.y, nM2));
            float u2 = ex2(l2m);
            float gap = fabsf(u2 * invZ2 - ex2(l1m) * invZ1);
            float bfc = fminf(fmaxf(fmaf(l2m, invw1, bias1), 0.f), (float)(NBG - 1));
            if (bfc < b1f)        gt += gap;
            else if (bfc >= b1f1) gh += gap;
            else {
                float sf = fmaf(l2m, invw2, bias2);
                int s = (int)fminf(fmaxf(sf, 0.f), (float)(NB2 - 1));
                atomicAdd(&hist2[s], u2);
                int idx = atomicAdd(&s_cnt, 1);
                if (idx < CAP) { st_l2[idx] = l2m; st_u2[idx] = u2; st_gap[idx] = gap; }
            }
        }
    }

    // ---- Level-2 crossing within the smem sub-histogram
    find_crossing<NB2, BPT2>(hist2, red, halfZ2 - cdf1, &s_b2, &s_cdf2);
    const int   b2   = s_b2;
    const float cdf2 = cdf1 + s_cdf2;
    __syncthreads();
    const int m = s_cnt;

    if (m <= CAP) {
        for (int i = tid; i < m; i += NT) {
            float sf = fmaf(st_l2[i], invw2, bias2);
            int s = (int)fminf(fmaxf(sf, 0.f), (float)(NB2 - 1));
            bool tail;
            if (s != b2) tail = (s < b2);
            else         tail = (cdf2 + st_u2[i]) < halfZ2;
            if (tail) gt += st_gap[i]; else gh += st_gap[i];
        }
    } else {
        // Rare degenerate row: exact rescan of crossing-bin elements
        for (int j = tid; j < CLS_NUM; j += NT) {
            float2 v3 = __ldg(e3v + j);
            float l2m = fmaf(a3, v3.x, fmaf(b3v, v3.y, nM2));
            float bfc = fminf(fmaxf(fmaf(l2m, invw1, bias1), 0.f), (float)(NBG - 1));
            if (bfc >= b1f && bfc < b1f1) {
                float2 v1 = __ldg(e1v + j);
                float l1m = fmaf(a1, v1.x, fmaf(b1v, v1.y, nM1));
                float u2 = ex2(l2m);
                float gap = fabsf(u2 * invZ2 - ex2(l1m) * invZ1);
                float sf = fmaf(l2m, invw2, bias2);
                int s = (int)fminf(fmaxf(sf, 0.f), (float)(NB2 - 1));
                bool tail;
                if (s != b2) tail = (s < b2);
                else         tail = (cdf2 + u2) < halfZ2;
                if (tail) gt += gap; else gh += gap;
            }
        }
    }
    gh = block_sum(gh, red);
    gt = block_sum(gt, red);

    if (tid == 0) {
        // log2-domain sums -> nats
        float C21 = LN2 * (M2 - M1) + (__logf(Z2) - __logf(Z1));
        float fkl = LN2 * S2 / Z2 - C21;
        float rkl = LN2 * S1 / Z1 + C21;
        float denom = gh + gt;
        float akl = (gh * fkl + gt * rkl) / denom;
        atomicAdd(out, akl * (1.0f / (float)DATA_NUM));
    }
}

// ---------------------------------------------------------------------------
extern "C" void kernel_launch(void* const* d_in, const int* in_sizes, int n_in,
                              void* d_out, int out_size) {
    const float *h1 = 0, *h3 = 0, *e1 = 0, *e3 = 0;
    for (int i = 0; i < n_in; i++) {
        int s = in_sizes[i];
        if (s == 2 * DATA_NUM || s == 2 * DATA_NUM * 4) {
            if (!h1) h1 = (const float*)d_in[i]; else if (!h3) h3 = (const float*)d_in[i];
        } else if (s == 2 * CLS_NUM || s == 2 * CLS_NUM * 4) {
            if (!e1) e1 = (const float*)d_in[i]; else if (!e3) e3 = (const float*)d_in[i];
        }
    }
    if (!h1 || !h3 || !e1 || !e3) {
        h1 = (const float*)d_in[0];
        e1 = (const float*)d_in[1];
        h3 = (const float*)d_in[2];
        e3 = (const float*)d_in[3];
    }

    float* out = (float*)d_out;
    zero_out<<<1, 1>>>(out);
    akl_kernel<<<DATA_NUM, NT>>>(h1, e1, h3, e3, out);
}